// round 1
// baseline (speedup 1.0000x reference)
#include <cuda_runtime.h>
#include <cuda_bf16.h>
#include <math.h>

// Problem constants
#define B_ 4
#define S_ 2048
#define DM 1024
#define NH 16
#define DK 64
#define M_PROJ (B_ * S_)            // 8192
#define OUT_ELEMS ((size_t)B_ * S_ * DM)            // 8,388,608
#define ATTN_ELEMS ((size_t)B_ * NH * S_ * S_)      // 268,435,456

// Scratch (no cudaMalloc allowed): head-split Q/K/V [B,H,S,DK] and context [B,S,DM]
__device__ float g_Q[B_ * NH * S_ * DK];
__device__ float g_K[B_ * NH * S_ * DK];
__device__ float g_V[B_ * NH * S_ * DK];
__device__ float g_ctx[(size_t)B_ * S_ * DM];

// ---------------------------------------------------------------------------
// GEMM: out[M,N] = A[M,K] @ W[K,N] + bias[N], M=8192, N=K=1024.
// headsplit=1 -> write into [B,H,S,DK] layout; headsplit=0 -> plain [M,N].
// Tile 64x64x16, 256 threads, 4x4 per thread.
// ---------------------------------------------------------------------------
__global__ __launch_bounds__(256) void gemm_proj(
    const float* __restrict__ A, const float* __restrict__ W,
    const float* __restrict__ bias, float* __restrict__ out, int headsplit)
{
    const int K = DM, N = DM;
    __shared__ float As[64][17];   // [m][k], +1 pad
    __shared__ float Bs[16][65];   // [k][n], +1 pad

    const int tid = threadIdx.x;
    const int tx = tid & 15, ty = tid >> 4;
    const int bm = blockIdx.y * 64, bn = blockIdx.x * 64;

    float acc[4][4] = {};

    for (int k0 = 0; k0 < K; k0 += 16) {
        // A tile 64x16: thread -> row tid>>2, 4 consecutive cols
        {
            int r = tid >> 2;
            int c = (tid & 3) * 4;
            float4 v = *reinterpret_cast<const float4*>(
                A + (size_t)(bm + r) * K + k0 + c);
            As[r][c] = v.x; As[r][c + 1] = v.y; As[r][c + 2] = v.z; As[r][c + 3] = v.w;
        }
        // B tile 16x64: thread -> row tid>>4, 4 consecutive cols
        {
            int r = tid >> 4;
            int c = (tid & 15) * 4;
            float4 v = *reinterpret_cast<const float4*>(
                W + (size_t)(k0 + r) * N + bn + c);
            Bs[r][c] = v.x; Bs[r][c + 1] = v.y; Bs[r][c + 2] = v.z; Bs[r][c + 3] = v.w;
        }
        __syncthreads();
        #pragma unroll
        for (int k = 0; k < 16; ++k) {
            float a[4], b[4];
            #pragma unroll
            for (int i = 0; i < 4; ++i) a[i] = As[ty * 4 + i][k];
            #pragma unroll
            for (int j = 0; j < 4; ++j) b[j] = Bs[k][tx * 4 + j];
            #pragma unroll
            for (int i = 0; i < 4; ++i)
                #pragma unroll
                for (int j = 0; j < 4; ++j)
                    acc[i][j] = fmaf(a[i], b[j], acc[i][j]);
        }
        __syncthreads();
    }

    #pragma unroll
    for (int i = 0; i < 4; ++i) {
        int m = bm + ty * 4 + i;
        #pragma unroll
        for (int j = 0; j < 4; ++j) {
            int n = bn + tx * 4 + j;
            float v = acc[i][j] + bias[n];
            if (headsplit) {
                int b = m >> 11;          // m / S_
                int s = m & (S_ - 1);
                int h = n >> 6;           // n / DK
                int d = n & (DK - 1);
                out[(((size_t)b * NH + h) * S_ + s) * DK + d] = v;
            } else {
                out[(size_t)m * DM + n] = v;
            }
        }
    }
}

// ---------------------------------------------------------------------------
// scores[bh, q, k] = (Q[bh,q,:] . K[bh,k,:]) * 0.125   (raw, pre-softmax)
// grid (S/64 ktiles, S/64 qtiles, B*H); 256 threads; full d_k=64 in smem.
// ---------------------------------------------------------------------------
__global__ __launch_bounds__(256) void scores_kernel(
    const float* __restrict__ Q, const float* __restrict__ Kmat,
    float* __restrict__ attn)
{
    const int bh = blockIdx.z;
    const float* Qb = Q + (size_t)bh * S_ * DK;
    const float* Kb = Kmat + (size_t)bh * S_ * DK;

    __shared__ float Qs[64][65];
    __shared__ float Ks[64][65];

    const int tid = threadIdx.x;
    const int tx = tid & 15, ty = tid >> 4;
    const int q0 = blockIdx.y * 64, k0 = blockIdx.x * 64;

    // Load both 64x64 tiles (16 floats per thread each, via float4)
    #pragma unroll
    for (int i = 0; i < 4; ++i) {
        int idx = tid + i * 256;       // 0..1023 float4 slots
        int r = idx >> 4;
        int c = (idx & 15) * 4;
        float4 v = *reinterpret_cast<const float4*>(Qb + (size_t)(q0 + r) * DK + c);
        Qs[r][c] = v.x; Qs[r][c + 1] = v.y; Qs[r][c + 2] = v.z; Qs[r][c + 3] = v.w;
        float4 w = *reinterpret_cast<const float4*>(Kb + (size_t)(k0 + r) * DK + c);
        Ks[r][c] = w.x; Ks[r][c + 1] = w.y; Ks[r][c + 2] = w.z; Ks[r][c + 3] = w.w;
    }
    __syncthreads();

    float acc[4][4] = {};
    #pragma unroll 8
    for (int k = 0; k < 64; ++k) {
        float a[4], b[4];
        #pragma unroll
        for (int i = 0; i < 4; ++i) a[i] = Qs[ty * 4 + i][k];
        #pragma unroll
        for (int j = 0; j < 4; ++j) b[j] = Ks[tx * 4 + j][k];
        #pragma unroll
        for (int i = 0; i < 4; ++i)
            #pragma unroll
            for (int j = 0; j < 4; ++j)
                acc[i][j] = fmaf(a[i], b[j], acc[i][j]);
    }

    const float scale = 0.125f;   // 1/sqrt(64)
    float* base = attn + (size_t)bh * S_ * S_;
    #pragma unroll
    for (int i = 0; i < 4; ++i) {
        int q = q0 + ty * 4 + i;
        #pragma unroll
        for (int j = 0; j < 4; ++j) {
            int kk = k0 + tx * 4 + j;
            base[(size_t)q * S_ + kk] = acc[i][j] * scale;
        }
    }
}

// ---------------------------------------------------------------------------
// In-place row softmax over 2048 elements. One block (256 thr) per row.
// ---------------------------------------------------------------------------
__global__ __launch_bounds__(256) void softmax_kernel(float* __restrict__ attn)
{
    float* p = attn + (size_t)blockIdx.x * S_;
    const int tid = threadIdx.x;
    const int warp = tid >> 5, lane = tid & 31;

    float v[8];
    float m = -INFINITY;
    #pragma unroll
    for (int i = 0; i < 8; ++i) {
        v[i] = p[tid + i * 256];
        m = fmaxf(m, v[i]);
    }
    #pragma unroll
    for (int o = 16; o > 0; o >>= 1) m = fmaxf(m, __shfl_xor_sync(0xFFFFFFFFu, m, o));

    __shared__ float smax[8];
    __shared__ float ssum[8];
    if (lane == 0) smax[warp] = m;
    __syncthreads();
    m = smax[0];
    #pragma unroll
    for (int i = 1; i < 8; ++i) m = fmaxf(m, smax[i]);

    float s = 0.f;
    #pragma unroll
    for (int i = 0; i < 8; ++i) {
        v[i] = __expf(v[i] - m);
        s += v[i];
    }
    #pragma unroll
    for (int o = 16; o > 0; o >>= 1) s += __shfl_xor_sync(0xFFFFFFFFu, s, o);
    if (lane == 0) ssum[warp] = s;
    __syncthreads();
    s = ssum[0];
    #pragma unroll
    for (int i = 1; i < 8; ++i) s += ssum[i];

    const float inv = 1.0f / s;
    #pragma unroll
    for (int i = 0; i < 8; ++i) p[tid + i * 256] = v[i] * inv;
}

// ---------------------------------------------------------------------------
// context[b, s, h*64+d] = sum_k attn[bh, s, k] * V[bh, k, d]
// Per (b,h): GEMM [2048 x 2048] @ [2048 x 64]. Tile 64x64x16.
// grid (S/64 qtiles, B*H)
// ---------------------------------------------------------------------------
__global__ __launch_bounds__(256) void av_kernel(
    const float* __restrict__ attn, const float* __restrict__ V,
    float* __restrict__ ctx)
{
    const int bh = blockIdx.y;
    const int q0 = blockIdx.x * 64;
    const float* Ab = attn + (size_t)bh * S_ * S_;
    const float* Vb = V + (size_t)bh * S_ * DK;

    __shared__ float As[64][17];
    __shared__ float Bs[16][65];

    const int tid = threadIdx.x;
    const int tx = tid & 15, ty = tid >> 4;

    float acc[4][4] = {};

    for (int k0 = 0; k0 < S_; k0 += 16) {
        {
            int r = tid >> 2;
            int c = (tid & 3) * 4;
            float4 v = *reinterpret_cast<const float4*>(
                Ab + (size_t)(q0 + r) * S_ + k0 + c);
            As[r][c] = v.x; As[r][c + 1] = v.y; As[r][c + 2] = v.z; As[r][c + 3] = v.w;
        }
        {
            int r = tid >> 4;
            int c = (tid & 15) * 4;
            float4 v = *reinterpret_cast<const float4*>(
                Vb + (size_t)(k0 + r) * DK + c);
            Bs[r][c] = v.x; Bs[r][c + 1] = v.y; Bs[r][c + 2] = v.z; Bs[r][c + 3] = v.w;
        }
        __syncthreads();
        #pragma unroll
        for (int k = 0; k < 16; ++k) {
            float a[4], b[4];
            #pragma unroll
            for (int i = 0; i < 4; ++i) a[i] = As[ty * 4 + i][k];
            #pragma unroll
            for (int j = 0; j < 4; ++j) b[j] = Bs[k][tx * 4 + j];
            #pragma unroll
            for (int i = 0; i < 4; ++i)
                #pragma unroll
                for (int j = 0; j < 4; ++j)
                    acc[i][j] = fmaf(a[i], b[j], acc[i][j]);
        }
        __syncthreads();
    }

    const int b = bh >> 4;        // bh / NH
    const int h = bh & (NH - 1);
    #pragma unroll
    for (int i = 0; i < 4; ++i) {
        int s = q0 + ty * 4 + i;
        #pragma unroll
        for (int j = 0; j < 4; ++j) {
            int d = tx * 4 + j;
            ctx[((size_t)b * S_ + s) * DM + h * DK + d] = acc[i][j];
        }
    }
}

// ---------------------------------------------------------------------------
extern "C" void kernel_launch(void* const* d_in, const int* in_sizes, int n_in,
                              void* d_out, int out_size)
{
    const float* query = (const float*)d_in[0];
    const float* key   = (const float*)d_in[1];
    const float* value = (const float*)d_in[2];
    const float* w_q = (const float*)d_in[3];
    const float* b_q = (const float*)d_in[4];
    const float* w_k = (const float*)d_in[5];
    const float* b_k = (const float*)d_in[6];
    const float* w_v = (const float*)d_in[7];
    const float* b_v = (const float*)d_in[8];
    const float* w_o = (const float*)d_in[9];
    const float* b_o = (const float*)d_in[10];

    float* out = (float*)d_out;
    // Reference returns (output, attn); harness concatenates flattened outputs.
    float* attn = out + OUT_ELEMS;

    float* Qp; cudaGetSymbolAddress((void**)&Qp, g_Q);
    float* Kp; cudaGetSymbolAddress((void**)&Kp, g_K);
    float* Vp; cudaGetSymbolAddress((void**)&Vp, g_V);
    float* Cp; cudaGetSymbolAddress((void**)&Cp, g_ctx);

    dim3 gproj(DM / 64, M_PROJ / 64);   // (16, 128)

    gemm_proj<<<gproj, 256>>>(query, w_q, b_q, Qp, 1);
    gemm_proj<<<gproj, 256>>>(key,   w_k, b_k, Kp, 1);
    gemm_proj<<<gproj, 256>>>(value, w_v, b_v, Vp, 1);

    scores_kernel<<<dim3(S_ / 64, S_ / 64, B_ * NH), 256>>>(Qp, Kp, attn);

    softmax_kernel<<<B_ * NH * S_, 256>>>(attn);

    av_kernel<<<dim3(S_ / 64, B_ * NH), 256>>>(attn, Vp, Cp);

    gemm_proj<<<gproj, 256>>>(Cp, w_o, b_o, out, 0);
}

// round 2
// speedup vs baseline: 2.8906x; 2.8906x over previous
#include <cuda_runtime.h>
#include <math.h>

// Problem constants
#define B_ 4
#define S_ 2048
#define DM 1024
#define NH 16
#define DK 64
#define OUT_ELEMS ((size_t)B_ * S_ * DM)            // 8,388,608

// Scratch (no cudaMalloc allowed)
__device__ float g_Q[B_ * NH * S_ * DK];
__device__ float g_K[B_ * NH * S_ * DK];
__device__ float g_V[B_ * NH * S_ * DK];
__device__ float g_ctx[(size_t)B_ * S_ * DM];

__device__ __forceinline__ unsigned f2tf(float x) {
    unsigned u;
    asm("cvt.rna.tf32.f32 %0, %1;" : "=r"(u) : "f"(x));
    return u;
}

__device__ __forceinline__ void mma8(float* c, const unsigned* a, const unsigned* b) {
    asm volatile(
        "mma.sync.aligned.m16n8k8.row.col.f32.tf32.tf32.f32 "
        "{%0,%1,%2,%3}, {%4,%5,%6,%7}, {%8,%9}, {%0,%1,%2,%3};"
        : "+f"(c[0]), "+f"(c[1]), "+f"(c[2]), "+f"(c[3])
        : "r"(a[0]), "r"(a[1]), "r"(a[2]), "r"(a[3]), "r"(b[0]), "r"(b[1]));
}

// ---------------------------------------------------------------------------
// Generic tf32 MMA GEMM.
// A: [M,K] row-major (lda), per-z batch offset abatch.
// B: MODE_B==0 -> [K,N] row-major (ldb);  MODE_B==1 -> [N,K] row-major (ldb).
// EPI: 0 = +bias, head-split store (proj Q/K/V)
//      1 = +bias, plain [M, DM] store (proj O)
//      2 = *scale, store to attn (z = bh, row stride S_)
//      3 = store to ctx at [ (z/16)*S + m ][ (z%16)*DK + n ], row stride DM
// ---------------------------------------------------------------------------
template<int BM, int BN, int BK, int WM, int WN, int MODE_B, int EPI>
__global__ void __launch_bounds__((BM / WM) * (BN / WN) * 32)
gemm_mma(const float* __restrict__ A, int lda, size_t abatch,
         const float* __restrict__ Bm, int ldb, size_t bbatch,
         float* __restrict__ C, const float* __restrict__ bias,
         float scale, int K)
{
    constexpr int WARPS_M = BM / WM, WARPS_N = BN / WN;
    constexpr int T = WARPS_M * WARPS_N * 32;
    constexpr int SA = BK + 4;                          // A smem stride
    constexpr int SB = (MODE_B == 0) ? (BN + 8) : (BK + 4);
    constexpr int BROWS = (MODE_B == 0) ? BK : BN;

    __shared__ unsigned As[BM * SA];
    __shared__ unsigned Bs[BROWS * SB];

    const int tid = threadIdx.x;
    const int lane = tid & 31, wid = tid >> 5;
    const int wm = (wid % WARPS_M) * WM;
    const int wn = (wid / WARPS_M) * WN;
    const int bm = blockIdx.y * BM, bn = blockIdx.x * BN;
    const int z = blockIdx.z;

    const float* Ap = A + (size_t)z * abatch;
    const float* Bp = Bm + (size_t)z * bbatch;

    constexpr int MI = WM / 16, NI = WN / 8;
    float acc[MI][NI][4] = {};

    constexpr int LA = BM * BK / (T * 4);
    constexpr int LB = BK * BN / (T * 4);
    float4 ra[LA], rb[LB];

    auto loadA = [&](int k0) {
        #pragma unroll
        for (int i = 0; i < LA; ++i) {
            int f = tid + i * T;
            int r = f / (BK / 4), c = (f % (BK / 4)) * 4;
            ra[i] = *reinterpret_cast<const float4*>(Ap + (size_t)(bm + r) * lda + k0 + c);
        }
    };
    auto storeA = [&]() {
        #pragma unroll
        for (int i = 0; i < LA; ++i) {
            int f = tid + i * T;
            int r = f / (BK / 4), c = (f % (BK / 4)) * 4;
            unsigned* p = &As[r * SA + c];
            p[0] = f2tf(ra[i].x); p[1] = f2tf(ra[i].y);
            p[2] = f2tf(ra[i].z); p[3] = f2tf(ra[i].w);
        }
    };
    auto loadB = [&](int k0) {
        #pragma unroll
        for (int i = 0; i < LB; ++i) {
            int f = tid + i * T;
            if (MODE_B == 0) {
                int r = f / (BN / 4), c = (f % (BN / 4)) * 4;   // r = k, c = n
                rb[i] = *reinterpret_cast<const float4*>(Bp + (size_t)(k0 + r) * ldb + bn + c);
            } else {
                int r = f / (BK / 4), c = (f % (BK / 4)) * 4;   // r = n, c = k
                rb[i] = *reinterpret_cast<const float4*>(Bp + (size_t)(bn + r) * ldb + k0 + c);
            }
        }
    };
    auto storeB = [&]() {
        #pragma unroll
        for (int i = 0; i < LB; ++i) {
            int f = tid + i * T;
            unsigned* p;
            if (MODE_B == 0) {
                int r = f / (BN / 4), c = (f % (BN / 4)) * 4;
                p = &Bs[r * SB + c];
            } else {
                int r = f / (BK / 4), c = (f % (BK / 4)) * 4;
                p = &Bs[r * SB + c];
            }
            p[0] = f2tf(rb[i].x); p[1] = f2tf(rb[i].y);
            p[2] = f2tf(rb[i].z); p[3] = f2tf(rb[i].w);
        }
    };

    loadA(0);
    loadB(0);
    const int KIT = K / BK;

    for (int it = 0; it < KIT; ++it) {
        storeA();
        storeB();
        __syncthreads();
        if (it + 1 < KIT) { loadA((it + 1) * BK); loadB((it + 1) * BK); }

        #pragma unroll
        for (int kk = 0; kk < BK / 8; ++kk) {
            unsigned afr[MI][4], bfr[NI][2];
            #pragma unroll
            for (int mi = 0; mi < MI; ++mi) {
                int r = wm + mi * 16 + (lane >> 2);
                int c = kk * 8 + (lane & 3);
                afr[mi][0] = As[r * SA + c];
                afr[mi][1] = As[(r + 8) * SA + c];
                afr[mi][2] = As[r * SA + c + 4];
                afr[mi][3] = As[(r + 8) * SA + c + 4];
            }
            #pragma unroll
            for (int ni = 0; ni < NI; ++ni) {
                int n = wn + ni * 8 + (lane >> 2);
                int c = kk * 8 + (lane & 3);
                if (MODE_B == 0) {
                    bfr[ni][0] = Bs[c * SB + n];
                    bfr[ni][1] = Bs[(c + 4) * SB + n];
                } else {
                    bfr[ni][0] = Bs[n * SB + c];
                    bfr[ni][1] = Bs[n * SB + c + 4];
                }
            }
            #pragma unroll
            for (int mi = 0; mi < MI; ++mi)
                #pragma unroll
                for (int ni = 0; ni < NI; ++ni)
                    mma8(acc[mi][ni], afr[mi], bfr[ni]);
        }
        __syncthreads();
    }

    // Epilogue
    #pragma unroll
    for (int mi = 0; mi < MI; ++mi) {
        #pragma unroll
        for (int ni = 0; ni < NI; ++ni) {
            #pragma unroll
            for (int e = 0; e < 4; ++e) {
                int m = bm + wm + mi * 16 + (lane >> 2) + ((e >= 2) ? 8 : 0);
                int n = bn + wn + ni * 8 + (lane & 3) * 2 + (e & 1);
                float v = acc[mi][ni][e];
                if (EPI == 0) {
                    v += bias[n];
                    int b = m >> 11, s = m & (S_ - 1);
                    int h = n >> 6, d = n & (DK - 1);
                    C[(((size_t)b * NH + h) * S_ + s) * DK + d] = v;
                } else if (EPI == 1) {
                    v += bias[n];
                    C[(size_t)m * DM + n] = v;
                } else if (EPI == 2) {
                    C[(size_t)z * S_ * S_ + (size_t)m * S_ + n] = v * scale;
                } else {
                    C[((size_t)(z >> 4) * S_ + m) * DM + (z & (NH - 1)) * DK + n] = v;
                }
            }
        }
    }
}

// ---------------------------------------------------------------------------
// In-place row softmax over 2048 elements. One block (256 thr) per row.
// ---------------------------------------------------------------------------
__global__ void __launch_bounds__(256) softmax_kernel(float* __restrict__ attn)
{
    float* p = attn + (size_t)blockIdx.x * S_;
    const int tid = threadIdx.x;
    const int warp = tid >> 5, lane = tid & 31;

    float v[8];
    float m = -INFINITY;
    #pragma unroll
    for (int i = 0; i < 8; ++i) {
        v[i] = p[tid + i * 256];
        m = fmaxf(m, v[i]);
    }
    #pragma unroll
    for (int o = 16; o > 0; o >>= 1) m = fmaxf(m, __shfl_xor_sync(0xFFFFFFFFu, m, o));

    __shared__ float smax[8];
    __shared__ float ssum[8];
    if (lane == 0) smax[warp] = m;
    __syncthreads();
    m = smax[0];
    #pragma unroll
    for (int i = 1; i < 8; ++i) m = fmaxf(m, smax[i]);

    float s = 0.f;
    #pragma unroll
    for (int i = 0; i < 8; ++i) {
        v[i] = __expf(v[i] - m);
        s += v[i];
    }
    #pragma unroll
    for (int o = 16; o > 0; o >>= 1) s += __shfl_xor_sync(0xFFFFFFFFu, s, o);
    if (lane == 0) ssum[warp] = s;
    __syncthreads();
    s = ssum[0];
    #pragma unroll
    for (int i = 1; i < 8; ++i) s += ssum[i];

    const float inv = 1.0f / s;
    #pragma unroll
    for (int i = 0; i < 8; ++i) p[tid + i * 256] = v[i] * inv;
}

// ---------------------------------------------------------------------------
extern "C" void kernel_launch(void* const* d_in, const int* in_sizes, int n_in,
                              void* d_out, int out_size)
{
    const float* query = (const float*)d_in[0];
    const float* key   = (const float*)d_in[1];
    const float* value = (const float*)d_in[2];
    const float* w_q = (const float*)d_in[3];
    const float* b_q = (const float*)d_in[4];
    const float* w_k = (const float*)d_in[5];
    const float* b_k = (const float*)d_in[6];
    const float* w_v = (const float*)d_in[7];
    const float* b_v = (const float*)d_in[8];
    const float* w_o = (const float*)d_in[9];
    const float* b_o = (const float*)d_in[10];

    float* out = (float*)d_out;
    float* attn = out + OUT_ELEMS;   // (output, attn) concatenated

    float* Qp; cudaGetSymbolAddress((void**)&Qp, g_Q);
    float* Kp; cudaGetSymbolAddress((void**)&Kp, g_K);
    float* Vp; cudaGetSymbolAddress((void**)&Vp, g_V);
    float* Cp; cudaGetSymbolAddress((void**)&Cp, g_ctx);

    // Q/K/V projections: [8192,1024] @ [1024,1024] + bias, head-split store
    dim3 gproj(DM / 128, (B_ * S_) / 128, 1);   // (8, 64)
    gemm_mma<128,128,32,64,32,0,0><<<gproj, 256>>>(query, DM, 0, w_q, DM, 0, Qp, b_q, 1.f, DM);
    gemm_mma<128,128,32,64,32,0,0><<<gproj, 256>>>(key,   DM, 0, w_k, DM, 0, Kp, b_k, 1.f, DM);
    gemm_mma<128,128,32,64,32,0,0><<<gproj, 256>>>(value, DM, 0, w_v, DM, 0, Vp, b_v, 1.f, DM);

    // scores = Q @ K^T * 0.125 per (b,h): A=[2048,64], B(NK)=[2048,64]
    gemm_mma<128,128,32,64,32,1,2><<<dim3(S_ / 128, S_ / 128, B_ * NH), 256>>>(
        Qp, DK, (size_t)S_ * DK, Kp, DK, (size_t)S_ * DK, attn, nullptr, 0.125f, DK);

    softmax_kernel<<<B_ * NH * S_, 256>>>(attn);

    // ctx = attn @ V per (b,h): A=[2048,2048], B=[2048,64]
    gemm_mma<128,64,32,64,32,0,3><<<dim3(1, S_ / 128, B_ * NH), 128>>>(
        attn, S_, (size_t)S_ * S_, Vp, DK, (size_t)S_ * DK, Cp, nullptr, 1.f, S_);

    // output projection
    gemm_mma<128,128,32,64,32,0,1><<<gproj, 256>>>(Cp, DM, 0, w_o, DM, 0, out, b_o, 1.f, DM);
}

// round 3
// speedup vs baseline: 3.2156x; 1.1124x over previous
#include <cuda_runtime.h>
#include <math.h>

// Problem constants
#define B_ 4
#define S_ 2048
#define DM 1024
#define NH 16
#define DK 64
#define OUT_ELEMS ((size_t)B_ * S_ * DM)            // 8,388,608

// Scratch (no cudaMalloc allowed)
__device__ float g_Q[B_ * NH * S_ * DK];
__device__ float g_K[B_ * NH * S_ * DK];
__device__ float g_V[B_ * NH * S_ * DK];
__device__ float g_ctx[(size_t)B_ * S_ * DM];

__device__ __forceinline__ unsigned f2tf(float x) {
    unsigned u;
    asm("cvt.rna.tf32.f32 %0, %1;" : "=r"(u) : "f"(x));
    return u;
}

__device__ __forceinline__ void mma8(float* c, const unsigned* a, const unsigned* b) {
    asm volatile(
        "mma.sync.aligned.m16n8k8.row.col.f32.tf32.tf32.f32 "
        "{%0,%1,%2,%3}, {%4,%5,%6,%7}, {%8,%9}, {%0,%1,%2,%3};"
        : "+f"(c[0]), "+f"(c[1]), "+f"(c[2]), "+f"(c[3])
        : "r"(a[0]), "r"(a[1]), "r"(a[2]), "r"(a[3]), "r"(b[0]), "r"(b[1]));
}

// ---------------------------------------------------------------------------
// Projection GEMM (tf32 MMA): out[M,N] = A[M,K] @ W[K,N] + bias.
// EPI 0 = head-split store, EPI 1 = plain [M,DM] store.
// ---------------------------------------------------------------------------
template<int EPI>
__global__ void __launch_bounds__(256)
gemm_proj(const float* __restrict__ A, const float* __restrict__ W,
          float* __restrict__ C, const float* __restrict__ bias)
{
    constexpr int BM = 128, BN = 128, BK = 32;
    constexpr int SA = BK + 4, SB = BN + 8;
    __shared__ unsigned As[BM * SA];
    __shared__ unsigned Bs[BK * SB];

    const int tid = threadIdx.x;
    const int lane = tid & 31, wid = tid >> 5;
    const int wm = (wid & 1) * 64, wn = (wid >> 1) * 32;
    const int bm = blockIdx.y * BM, bn = blockIdx.x * BN;

    float acc[4][4][4] = {};
    float4 ra[4], rb[4];

    auto loadA = [&](int k0) {
        #pragma unroll
        for (int i = 0; i < 4; ++i) {
            int f = tid + i * 256;
            int r = f >> 3, c = (f & 7) * 4;
            ra[i] = *reinterpret_cast<const float4*>(A + (size_t)(bm + r) * DM + k0 + c);
        }
    };
    auto loadB = [&](int k0) {
        #pragma unroll
        for (int i = 0; i < 4; ++i) {
            int f = tid + i * 256;
            int r = f >> 5, c = (f & 31) * 4;
            rb[i] = *reinterpret_cast<const float4*>(W + (size_t)(k0 + r) * DM + bn + c);
        }
    };
    auto stage = [&]() {
        #pragma unroll
        for (int i = 0; i < 4; ++i) {
            int f = tid + i * 256;
            int r = f >> 3, c = (f & 7) * 4;
            unsigned* p = &As[r * SA + c];
            p[0] = f2tf(ra[i].x); p[1] = f2tf(ra[i].y); p[2] = f2tf(ra[i].z); p[3] = f2tf(ra[i].w);
            int r2 = f >> 5, c2 = (f & 31) * 4;
            unsigned* q = &Bs[r2 * SB + c2];
            q[0] = f2tf(rb[i].x); q[1] = f2tf(rb[i].y); q[2] = f2tf(rb[i].z); q[3] = f2tf(rb[i].w);
        }
    };

    loadA(0); loadB(0);
    for (int it = 0; it < DM / BK; ++it) {
        stage();
        __syncthreads();
        if (it + 1 < DM / BK) { loadA((it + 1) * BK); loadB((it + 1) * BK); }

        #pragma unroll
        for (int kk = 0; kk < BK / 8; ++kk) {
            unsigned afr[4][4], bfr[4][2];
            #pragma unroll
            for (int mi = 0; mi < 4; ++mi) {
                int r = wm + mi * 16 + (lane >> 2);
                int c = kk * 8 + (lane & 3);
                afr[mi][0] = As[r * SA + c];
                afr[mi][1] = As[(r + 8) * SA + c];
                afr[mi][2] = As[r * SA + c + 4];
                afr[mi][3] = As[(r + 8) * SA + c + 4];
            }
            #pragma unroll
            for (int ni = 0; ni < 4; ++ni) {
                int n = wn + ni * 8 + (lane >> 2);
                int c = kk * 8 + (lane & 3);
                bfr[ni][0] = Bs[c * SB + n];
                bfr[ni][1] = Bs[(c + 4) * SB + n];
            }
            #pragma unroll
            for (int mi = 0; mi < 4; ++mi)
                #pragma unroll
                for (int ni = 0; ni < 4; ++ni)
                    mma8(acc[mi][ni], afr[mi], bfr[ni]);
        }
        __syncthreads();
    }

    #pragma unroll
    for (int mi = 0; mi < 4; ++mi)
        #pragma unroll
        for (int ni = 0; ni < 4; ++ni)
            #pragma unroll
            for (int e = 0; e < 4; ++e) {
                int m = bm + wm + mi * 16 + (lane >> 2) + ((e >= 2) ? 8 : 0);
                int n = bn + wn + ni * 8 + (lane & 3) * 2 + (e & 1);
                float v = acc[mi][ni][e] + bias[n];
                if (EPI == 0) {
                    int b = m >> 11, s = m & (S_ - 1);
                    int h = n >> 6, d = n & (DK - 1);
                    C[(((size_t)b * NH + h) * S_ + s) * DK + d] = v;
                } else {
                    C[(size_t)m * DM + n] = v;
                }
            }
}

// ---------------------------------------------------------------------------
// Fused attention: per CTA = 128 q-rows of one (b,h).
// Pass 1: stream K tiles, QK^T MMA, online row max/sum (no gmem writes).
// Pass 2: recompute QK^T, p = exp(x-M)/S, write final attn, accumulate P@V.
// ---------------------------------------------------------------------------
#define QS_STRIDE 68
#define PS_STRIDE 132
#define FUSED_SMEM (128*68*4 /*Q*/ + 128*68*4 /*K*/ + 64*132*4 /*Vt*/ + 128*132*4 /*P*/)

__global__ void __launch_bounds__(256, 1)
fused_attn(const float* __restrict__ Q, const float* __restrict__ Km,
           const float* __restrict__ V, float* __restrict__ attn,
           float* __restrict__ ctx)
{
    extern __shared__ unsigned char smem_raw[];
    unsigned* Qs = (unsigned*)smem_raw;                       // [128][68]
    unsigned* Ks = Qs + 128 * QS_STRIDE;                      // [128][68]
    unsigned* Vt = Ks + 128 * QS_STRIDE;                      // [64][132] (d-major)
    unsigned* Ps = Vt + 64 * PS_STRIDE;                       // [128][132]
    // reduction scratch overlaps Ps (unused until pass 2)
    float* rowm  = (float*)Ps;          // [128][4]
    float* rowss = rowm + 128 * 4;      // [128][4]
    float* sM    = rowss + 128 * 4;     // [128]
    float* sSinv = sM + 128;            // [128]

    const int tid = threadIdx.x;
    const int lane = tid & 31, wid = tid >> 5;
    const int wm = (wid & 1) * 64;          // scores warp row
    const int wn = (wid >> 1) * 32;         // scores warp col
    const int wn2 = (wid >> 1) * 16;        // AV warp col
    const int q0 = blockIdx.x * 128;
    const int bh = blockIdx.y;
    const float scale = 0.125f;

    const float* Qb = Q + (size_t)bh * S_ * DK;
    const float* Kb = Km + (size_t)bh * S_ * DK;
    const float* Vb = V + (size_t)bh * S_ * DK;

    // Load Q tile (128 x 64) as tf32
    #pragma unroll
    for (int i = 0; i < 8; ++i) {
        int f = tid + i * 256;
        int r = f >> 4, c = (f & 15) * 4;
        float4 v = *reinterpret_cast<const float4*>(Qb + (size_t)(q0 + r) * DK + c);
        unsigned* p = &Qs[r * QS_STRIDE + c];
        p[0] = f2tf(v.x); p[1] = f2tf(v.y); p[2] = f2tf(v.z); p[3] = f2tf(v.w);
    }

    float mreg[4][2], sreg[4][2];
    #pragma unroll
    for (int mi = 0; mi < 4; ++mi)
        #pragma unroll
        for (int e = 0; e < 2; ++e) { mreg[mi][e] = -INFINITY; sreg[mi][e] = 0.f; }

    // ---------------- Pass 1: row max + sum ----------------
    for (int t = 0; t < S_ / 128; ++t) {
        __syncthreads();   // protect Ks from previous iteration's readers
        #pragma unroll
        for (int i = 0; i < 8; ++i) {
            int f = tid + i * 256;
            int r = f >> 4, c = (f & 15) * 4;
            float4 v = *reinterpret_cast<const float4*>(Kb + (size_t)(t * 128 + r) * DK + c);
            unsigned* p = &Ks[r * QS_STRIDE + c];
            p[0] = f2tf(v.x); p[1] = f2tf(v.y); p[2] = f2tf(v.z); p[3] = f2tf(v.w);
        }
        __syncthreads();

        float sacc[4][4][4] = {};
        #pragma unroll
        for (int kk = 0; kk < 8; ++kk) {
            unsigned afr[4][4], bfr[4][2];
            #pragma unroll
            for (int mi = 0; mi < 4; ++mi) {
                int r = wm + mi * 16 + (lane >> 2);
                int c = kk * 8 + (lane & 3);
                afr[mi][0] = Qs[r * QS_STRIDE + c];
                afr[mi][1] = Qs[(r + 8) * QS_STRIDE + c];
                afr[mi][2] = Qs[r * QS_STRIDE + c + 4];
                afr[mi][3] = Qs[(r + 8) * QS_STRIDE + c + 4];
            }
            #pragma unroll
            for (int ni = 0; ni < 4; ++ni) {
                int n = wn + ni * 8 + (lane >> 2);
                int c = kk * 8 + (lane & 3);
                bfr[ni][0] = Ks[n * QS_STRIDE + c];
                bfr[ni][1] = Ks[n * QS_STRIDE + c + 4];
            }
            #pragma unroll
            for (int mi = 0; mi < 4; ++mi)
                #pragma unroll
                for (int ni = 0; ni < 4; ++ni)
                    mma8(sacc[mi][ni], afr[mi], bfr[ni]);
        }

        // online max/sum update
        #pragma unroll
        for (int mi = 0; mi < 4; ++mi)
            #pragma unroll
            for (int e = 0; e < 2; ++e) {
                float lm = -INFINITY;
                #pragma unroll
                for (int ni = 0; ni < 4; ++ni)
                    lm = fmaxf(lm, fmaxf(sacc[mi][ni][e * 2], sacc[mi][ni][e * 2 + 1]));
                lm *= scale;
                float nm = fmaxf(mreg[mi][e], lm);
                float add = 0.f;
                #pragma unroll
                for (int ni = 0; ni < 4; ++ni) {
                    add += __expf(sacc[mi][ni][e * 2] * scale - nm);
                    add += __expf(sacc[mi][ni][e * 2 + 1] * scale - nm);
                }
                sreg[mi][e] = sreg[mi][e] * __expf(mreg[mi][e] - nm) + add;
                mreg[mi][e] = nm;
            }
    }

    // ---------------- Cross-lane / cross-warp reduction ----------------
    #pragma unroll
    for (int mi = 0; mi < 4; ++mi)
        #pragma unroll
        for (int e = 0; e < 2; ++e) {
            float m = mreg[mi][e], s = sreg[mi][e];
            #pragma unroll
            for (int off = 1; off <= 2; off <<= 1) {
                float om = __shfl_xor_sync(0xFFFFFFFFu, m, off);
                float os = __shfl_xor_sync(0xFFFFFFFFu, s, off);
                float nm = fmaxf(m, om);
                s = s * __expf(m - nm) + os * __expf(om - nm);
                m = nm;
            }
            mreg[mi][e] = m; sreg[mi][e] = s;
        }
    __syncthreads();   // Ps region free now (pass-1 readers done)
    if ((lane & 3) == 0) {
        int g = wid >> 1;
        #pragma unroll
        for (int mi = 0; mi < 4; ++mi)
            #pragma unroll
            for (int e = 0; e < 2; ++e) {
                int r = wm + mi * 16 + (lane >> 2) + e * 8;
                rowm[r * 4 + g] = mreg[mi][e];
                rowss[r * 4 + g] = sreg[mi][e];
            }
    }
    __syncthreads();
    if (tid < 128) {
        float M = -INFINITY;
        #pragma unroll
        for (int g = 0; g < 4; ++g) M = fmaxf(M, rowm[tid * 4 + g]);
        float S = 0.f;
        #pragma unroll
        for (int g = 0; g < 4; ++g) S += rowss[tid * 4 + g] * __expf(rowm[tid * 4 + g] - M);
        sM[tid] = M;
        sSinv[tid] = 1.0f / S;
    }
    __syncthreads();

    float Mf[4][2], Sf[4][2];
    #pragma unroll
    for (int mi = 0; mi < 4; ++mi)
        #pragma unroll
        for (int e = 0; e < 2; ++e) {
            int r = wm + mi * 16 + (lane >> 2) + e * 8;
            Mf[mi][e] = sM[r];
            Sf[mi][e] = sSinv[r];
        }

    // ---------------- Pass 2: recompute, write attn, accumulate P@V ------
    float acco[4][2][4] = {};
    float* attn_b = attn + (size_t)bh * S_ * S_;
    const int b = bh >> 4, h = bh & (NH - 1);

    for (int t = 0; t < S_ / 128; ++t) {
        __syncthreads();   // previous tile's Ps/Vt/Ks readers done
        #pragma unroll
        for (int i = 0; i < 8; ++i) {
            int f = tid + i * 256;
            int r = f >> 4, c = (f & 15) * 4;
            float4 v = *reinterpret_cast<const float4*>(Kb + (size_t)(t * 128 + r) * DK + c);
            unsigned* p = &Ks[r * QS_STRIDE + c];
            p[0] = f2tf(v.x); p[1] = f2tf(v.y); p[2] = f2tf(v.z); p[3] = f2tf(v.w);
            float4 w = *reinterpret_cast<const float4*>(Vb + (size_t)(t * 128 + r) * DK + c);
            Vt[(c + 0) * PS_STRIDE + r] = f2tf(w.x);
            Vt[(c + 1) * PS_STRIDE + r] = f2tf(w.y);
            Vt[(c + 2) * PS_STRIDE + r] = f2tf(w.z);
            Vt[(c + 3) * PS_STRIDE + r] = f2tf(w.w);
        }
        __syncthreads();

        float sacc[4][4][4] = {};
        #pragma unroll
        for (int kk = 0; kk < 8; ++kk) {
            unsigned afr[4][4], bfr[4][2];
            #pragma unroll
            for (int mi = 0; mi < 4; ++mi) {
                int r = wm + mi * 16 + (lane >> 2);
                int c = kk * 8 + (lane & 3);
                afr[mi][0] = Qs[r * QS_STRIDE + c];
                afr[mi][1] = Qs[(r + 8) * QS_STRIDE + c];
                afr[mi][2] = Qs[r * QS_STRIDE + c + 4];
                afr[mi][3] = Qs[(r + 8) * QS_STRIDE + c + 4];
            }
            #pragma unroll
            for (int ni = 0; ni < 4; ++ni) {
                int n = wn + ni * 8 + (lane >> 2);
                int c = kk * 8 + (lane & 3);
                bfr[ni][0] = Ks[n * QS_STRIDE + c];
                bfr[ni][1] = Ks[n * QS_STRIDE + c + 4];
            }
            #pragma unroll
            for (int mi = 0; mi < 4; ++mi)
                #pragma unroll
                for (int ni = 0; ni < 4; ++ni)
                    mma8(sacc[mi][ni], afr[mi], bfr[ni]);
        }

        // p = exp(x - M) * Sinv ; write attn + stage into Ps
        #pragma unroll
        for (int mi = 0; mi < 4; ++mi) {
            #pragma unroll
            for (int ni = 0; ni < 4; ++ni) {
                int r0 = wm + mi * 16 + (lane >> 2);
                int c0 = wn + ni * 8 + (lane & 3) * 2;
                float p0 = __expf(sacc[mi][ni][0] * scale - Mf[mi][0]) * Sf[mi][0];
                float p1 = __expf(sacc[mi][ni][1] * scale - Mf[mi][0]) * Sf[mi][0];
                float p2 = __expf(sacc[mi][ni][2] * scale - Mf[mi][1]) * Sf[mi][1];
                float p3 = __expf(sacc[mi][ni][3] * scale - Mf[mi][1]) * Sf[mi][1];
                *reinterpret_cast<float2*>(attn_b + (size_t)(q0 + r0) * S_ + t * 128 + c0) =
                    make_float2(p0, p1);
                *reinterpret_cast<float2*>(attn_b + (size_t)(q0 + r0 + 8) * S_ + t * 128 + c0) =
                    make_float2(p2, p3);
                Ps[r0 * PS_STRIDE + c0] = f2tf(p0);
                Ps[r0 * PS_STRIDE + c0 + 1] = f2tf(p1);
                Ps[(r0 + 8) * PS_STRIDE + c0] = f2tf(p2);
                Ps[(r0 + 8) * PS_STRIDE + c0 + 1] = f2tf(p3);
            }
        }
        __syncthreads();

        // AV: acco[128 x 64] += P[128 x 128] @ V[128 x 64]
        #pragma unroll
        for (int kk = 0; kk < 16; ++kk) {
            unsigned afr[4][4], bfr[2][2];
            #pragma unroll
            for (int ni = 0; ni < 2; ++ni) {
                int n = wn2 + ni * 8 + (lane >> 2);
                int c = kk * 8 + (lane & 3);
                bfr[ni][0] = Vt[n * PS_STRIDE + c];
                bfr[ni][1] = Vt[n * PS_STRIDE + c + 4];
            }
            #pragma unroll
            for (int mi = 0; mi < 4; ++mi) {
                int r = wm + mi * 16 + (lane >> 2);
                int c = kk * 8 + (lane & 3);
                afr[mi][0] = Ps[r * PS_STRIDE + c];
                afr[mi][1] = Ps[(r + 8) * PS_STRIDE + c];
                afr[mi][2] = Ps[r * PS_STRIDE + c + 4];
                afr[mi][3] = Ps[(r + 8) * PS_STRIDE + c + 4];
            }
            #pragma unroll
            for (int mi = 0; mi < 4; ++mi)
                #pragma unroll
                for (int ni = 0; ni < 2; ++ni)
                    mma8(acco[mi][ni], afr[mi], bfr[ni]);
        }
    }

    // store ctx (already normalized)
    #pragma unroll
    for (int mi = 0; mi < 4; ++mi)
        #pragma unroll
        for (int ni = 0; ni < 2; ++ni)
            #pragma unroll
            for (int e = 0; e < 4; ++e) {
                int row = q0 + wm + mi * 16 + (lane >> 2) + ((e >= 2) ? 8 : 0);
                int d = wn2 + ni * 8 + (lane & 3) * 2 + (e & 1);
                ctx[((size_t)b * S_ + row) * DM + h * DK + d] = acco[mi][ni][e];
            }
}

// ---------------------------------------------------------------------------
extern "C" void kernel_launch(void* const* d_in, const int* in_sizes, int n_in,
                              void* d_out, int out_size)
{
    const float* query = (const float*)d_in[0];
    const float* key   = (const float*)d_in[1];
    const float* value = (const float*)d_in[2];
    const float* w_q = (const float*)d_in[3];
    const float* b_q = (const float*)d_in[4];
    const float* w_k = (const float*)d_in[5];
    const float* b_k = (const float*)d_in[6];
    const float* w_v = (const float*)d_in[7];
    const float* b_v = (const float*)d_in[8];
    const float* w_o = (const float*)d_in[9];
    const float* b_o = (const float*)d_in[10];

    float* out = (float*)d_out;
    float* attn = out + OUT_ELEMS;   // (output, attn) concatenated

    float* Qp; cudaGetSymbolAddress((void**)&Qp, g_Q);
    float* Kp; cudaGetSymbolAddress((void**)&Kp, g_K);
    float* Vp; cudaGetSymbolAddress((void**)&Vp, g_V);
    float* Cp; cudaGetSymbolAddress((void**)&Cp, g_ctx);

    cudaFuncSetAttribute(fused_attn, cudaFuncAttributeMaxDynamicSharedMemorySize,
                         FUSED_SMEM);

    dim3 gproj(DM / 128, (B_ * S_) / 128, 1);   // (8, 64)
    gemm_proj<0><<<gproj, 256>>>(query, w_q, Qp, b_q);
    gemm_proj<0><<<gproj, 256>>>(key,   w_k, Kp, b_k);
    gemm_proj<0><<<gproj, 256>>>(value, w_v, Vp, b_v);

    fused_attn<<<dim3(S_ / 128, B_ * NH), 256, FUSED_SMEM>>>(Qp, Kp, Vp, attn, Cp);

    gemm_proj<1><<<gproj, 256>>>(Cp, w_o, out, b_o);
}